// round 12
// baseline (speedup 1.0000x reference)
#include <cuda_runtime.h>
#include <cuda_bf16.h>

#define BATCH 2048
#define KLBL  20
#define NCLS  50257
#define TPB   512
#define NBLK  BATCH

// Scratch (no cudaMalloc allowed)
__device__ float g_part[BATCH];    // S_row - corr_row
__device__ float g_aux [BATCH];    // pos_mean per row
__device__ float g_cnt [BATCH];    // NCLS - U per row
__device__ int   g_counter = 0;    // last-block election; reset each replay

// ---------------------------------------------------------------------------
// exp(x), MUFU-free: magic-round + deg-2 Taylor + FMUL exponent scale.
// 7 fma-pipe ops + 2 ALU. Pointwise rel err <= 7e-3 worst-case; odd-order
// error cancels over the symmetric t-distribution -> measured loss rel_err
// 1.1e-4 (R6/R10), 9x inside the 1e-3 gate.
// ---------------------------------------------------------------------------
__device__ __forceinline__ float exp_fast(float x)
{
    float z  = fmaf(x, 1.4426950408889634f, 12582912.0f);   // magic 1.5*2^23
    float nf = z - 12582912.0f;                             // rint(x*log2e)
    float t  = fmaf(nf, -0.6931471805599453f, x);           // |t| <= 0.347
    float q  = fmaf(t, 0.5f, 1.0f);
    q = fmaf(q, t, 1.0f);                                   // 1 + t + t^2/2
    int sbits = (__float_as_int(z) << 23) + 0x3F800000;     // 2^n (wraps exact)
    return q * __int_as_float(sbits);
}

__device__ __forceinline__ void renorm(float& P, int& E)
{
    int b = __float_as_int(P);
    E += (b >> 23) - 127;
    P  = __int_as_float((b & 0x007FFFFF) | 0x3F800000);     // mantissa [1,2)
}

// ---------------------------------------------------------------------------
// One block per row (R2 loop shape, measured-best): S_row = log prod(1+e^x),
// fused label pass; last-block deterministic global combine.
// ---------------------------------------------------------------------------
__global__ __launch_bounds__(TPB)
void fused_row(const float* __restrict__ in, const int* __restrict__ tgt,
               float* __restrict__ out)
{
    const int row = blockIdx.x;
    const int tid = threadIdx.x;
    const float* p = in + (size_t)row * NCLS;

    __shared__ float sbuf[TPB];
    __shared__ int   slab[KLBL];
    __shared__ int   isLast;

    // label gathers issued early; latency hides under the stream
    if (tid < KLBL) slab[tid] = tgt[row * KLBL + tid];
    __syncthreads();
    float xlab = 0.0f;
    int   mylab = -1;
    if (tid < KLBL) { mylab = slab[tid]; xlab = __ldg(p + mylab); }

    float Pa = 1.0f, Pb = 1.0f;
    int   Ea = 0,   Eb = 0;

    // scalar head to reach 16B alignment: 50257 % 4 == 1 => offset row % 4
    const int h = (4 - (row & 3)) & 3;
    if (tid < h) { Pa = fmaf(exp_fast(p[tid]), Pa, Pa); renorm(Pa, Ea); }

    const int n4 = (NCLS - h) >> 2;
    const float4* v = (const float4*)(p + h);

    int i = tid;
    for (; i + TPB < n4; i += 2 * TPB) {
        float4 xa = v[i];          // both loads batched at loop head -> MLP=2
        float4 xb = v[i + TPB];
        Pa = fmaf(exp_fast(xa.x), Pa, Pa);
        Pa = fmaf(exp_fast(xa.y), Pa, Pa);
        Pb = fmaf(exp_fast(xa.z), Pb, Pb);
        Pb = fmaf(exp_fast(xa.w), Pb, Pb);
        Pa = fmaf(exp_fast(xb.x), Pa, Pa);
        Pa = fmaf(exp_fast(xb.y), Pa, Pa);
        Pb = fmaf(exp_fast(xb.z), Pb, Pb);
        Pb = fmaf(exp_fast(xb.w), Pb, Pb);
        renorm(Pa, Ea);            // 4 factors/acc: product < 2^40, safe
        renorm(Pb, Eb);
    }
    if (i < n4) {
        float4 xa = v[i];
        Pa = fmaf(exp_fast(xa.x), Pa, Pa);
        Pa = fmaf(exp_fast(xa.y), Pa, Pa);
        Pb = fmaf(exp_fast(xa.z), Pb, Pb);
        Pb = fmaf(exp_fast(xa.w), Pb, Pb);
        renorm(Pa, Ea);
        renorm(Pb, Eb);
    }
    const int tail = h + (n4 << 2);
    if (tid < NCLS - tail) {
        Pa = fmaf(exp_fast(p[tail + tid]), Pa, Pa);
        renorm(Pa, Ea);
    }

    float val = fmaf((float)(Ea + Eb), 0.69314718055994531f, __logf(Pa * Pb));

    // block tree reduce S_row
    sbuf[tid] = val;
    __syncthreads();
    #pragma unroll
    for (int r = TPB / 2; r > 0; r >>= 1) {
        if (tid < r) sbuf[tid] += sbuf[tid + r];
        __syncthreads();
    }

    // label pass on warp 0 (accurate math on 20 elements)
    if (tid < 32) {
        float pos = 0.0f, corr = 0.0f;
        int   U = 0;
        if (tid < KLBL) {
            float x  = xlab;
            float l1 = log1pf(__expf(-fabsf(x)));
            pos = -(fmaxf(-x, 0.0f) + l1);                    // log_sigmoid(x)
            bool uniq = true;
            #pragma unroll
            for (int j = 0; j < KLBL; j++)
                if (j < tid && slab[j] == mylab) uniq = false;
            if (uniq) { corr = fmaxf(x, 0.0f) + l1; U = 1; }  // softplus(x)
        }
        #pragma unroll
        for (int o = 16; o > 0; o >>= 1) {
            pos  += __shfl_down_sync(0xFFFFFFFF, pos,  o);
            corr += __shfl_down_sync(0xFFFFFFFF, corr, o);
            U    += __shfl_down_sync(0xFFFFFFFF, U,    o);
        }
        if (tid == 0) {
            g_part[row] = sbuf[0] - corr;
            g_aux[row]  = pos * (1.0f / (float)KLBL);
            g_cnt[row]  = (float)(NCLS - U);
        }
    }

    // last-block election + deterministic final combine
    if (tid == 0) {
        __threadfence();
        int t = atomicAdd(&g_counter, 1);
        isLast = (t == NBLK - 1);
    }
    __syncthreads();
    if (isLast) {
        float acc = 0.0f;
        for (int r = tid; r < BATCH; r += TPB)
            acc += g_aux[r] - g_part[r] / g_cnt[r];
        __syncthreads();
        sbuf[tid] = acc;
        __syncthreads();
        #pragma unroll
        for (int r = TPB / 2; r > 0; r >>= 1) {
            if (tid < r) sbuf[tid] += sbuf[tid + r];
            __syncthreads();
        }
        if (tid == 0) {
            out[0] = -sbuf[0] / (float)BATCH;
            g_counter = 0;          // reset for next graph replay
        }
    }
}

extern "C" void kernel_launch(void* const* d_in, const int* in_sizes, int n_in,
                              void* d_out, int out_size)
{
    const float* inputs  = (const float*)d_in[0];
    const int*   targets = (const int*)d_in[1];
    float*       out     = (float*)d_out;

    fused_row<<<NBLK, TPB>>>(inputs, targets, out);
}

// round 14
// speedup vs baseline: 1.0012x; 1.0012x over previous
#include <cuda_runtime.h>
#include <cuda_bf16.h>

#define BATCH 2048
#define KLBL  20
#define NCLS  50257
#define TPB   512
#define NBLK  BATCH

// Scratch (no cudaMalloc allowed)
__device__ float g_part[BATCH];    // S_row - corr_row
__device__ float g_aux [BATCH];    // pos_mean per row
__device__ float g_cnt [BATCH];    // NCLS - U per row
__device__ int   g_counter = 0;    // last-block election; reset each replay

// ---------------------------------------------------------------------------
// exp(x), MUFU-free: magic-round + deg-2 Taylor + FMUL exponent scale.
// Pointwise rel err <= 7e-3 worst-case; odd-order error cancels over the
// symmetric t-distribution -> measured loss rel_err 1.1e-4 (R6/R10/R11).
// ---------------------------------------------------------------------------
__device__ __forceinline__ float exp_fast(float x)
{
    float z  = fmaf(x, 1.4426950408889634f, 12582912.0f);   // magic 1.5*2^23
    float nf = z - 12582912.0f;                             // rint(x*log2e)
    float t  = fmaf(nf, -0.6931471805599453f, x);           // |t| <= 0.347
    float q  = fmaf(t, 0.5f, 1.0f);
    q = fmaf(q, t, 1.0f);                                   // 1 + t + t^2/2
    int sbits = (__float_as_int(z) << 23) + 0x3F800000;     // 2^n (wraps exact)
    return q * __int_as_float(sbits);
}

__device__ __forceinline__ void renorm(float& P, int& E)
{
    int b = __float_as_int(P);
    E += (b >> 23) - 127;
    P  = __int_as_float((b & 0x007FFFFF) | 0x3F800000);     // mantissa [1,2)
}

__device__ __forceinline__ void quad(const float4& x, float& Pa, float& Pb)
{
    Pa = fmaf(exp_fast(x.x), Pa, Pa);
    Pa = fmaf(exp_fast(x.y), Pa, Pa);
    Pb = fmaf(exp_fast(x.z), Pb, Pb);
    Pb = fmaf(exp_fast(x.w), Pb, Pb);
}

// ---------------------------------------------------------------------------
// One block per row: S_row = log prod(1+e^x) with MLP=4 batched loads;
// fused label pass; last-block deterministic global combine.
// ---------------------------------------------------------------------------
__global__ __launch_bounds__(TPB)
void fused_row(const float* __restrict__ in, const int* __restrict__ tgt,
               float* __restrict__ out)
{
    const int row = blockIdx.x;
    const int tid = threadIdx.x;
    const float* p = in + (size_t)row * NCLS;

    __shared__ float sbuf[TPB];
    __shared__ int   slab[KLBL];
    __shared__ int   isLast;

    // label gathers issued early; latency hides under the stream
    if (tid < KLBL) slab[tid] = tgt[row * KLBL + tid];
    __syncthreads();
    float xlab = 0.0f;
    int   mylab = -1;
    if (tid < KLBL) { mylab = slab[tid]; xlab = __ldg(p + mylab); }

    float Pa = 1.0f, Pb = 1.0f;
    int   Ea = 0,   Eb = 0;

    // scalar head to reach 16B alignment: 50257 % 4 == 1 => offset row % 4
    const int h = (4 - (row & 3)) & 3;
    if (tid < h) { Pa = fmaf(exp_fast(p[tid]), Pa, Pa); renorm(Pa, Ea); }

    const int n4 = (NCLS - h) >> 2;            // ~12564 float4
    const float4* v = (const float4*)(p + h);

    // main loop: 4 LDG.128 batched at loop head -> 4 outstanding loads/warp
    int i = tid;
    for (; i + 3 * TPB < n4; i += 4 * TPB) {
        float4 x0 = v[i];
        float4 x1 = v[i +     TPB];
        float4 x2 = v[i + 2 * TPB];
        float4 x3 = v[i + 3 * TPB];
        quad(x0, Pa, Pb);
        quad(x1, Pa, Pb);
        quad(x2, Pa, Pb);
        quad(x3, Pa, Pb);
        renorm(Pa, Ea);            // 8 factors/acc: product < 2^77, safe
        renorm(Pb, Eb);
    }
    // remainder float4s (< 4*TPB)
    for (; i < n4; i += TPB) {
        float4 x0 = v[i];
        quad(x0, Pa, Pb);
        renorm(Pa, Ea);
        renorm(Pb, Eb);
    }
    // scalar tail (<= 3)
    const int tail = h + (n4 << 2);
    if (tid < NCLS - tail) {
        Pa = fmaf(exp_fast(p[tail + tid]), Pa, Pa);
        renorm(Pa, Ea);
    }

    float val = fmaf((float)(Ea + Eb), 0.69314718055994531f, __logf(Pa * Pb));

    // block tree reduce S_row
    sbuf[tid] = val;
    __syncthreads();
    #pragma unroll
    for (int r = TPB / 2; r > 0; r >>= 1) {
        if (tid < r) sbuf[tid] += sbuf[tid + r];
        __syncthreads();
    }

    // label pass on warp 0 (accurate math on 20 elements)
    if (tid < 32) {
        float pos = 0.0f, corr = 0.0f;
        int   U = 0;
        if (tid < KLBL) {
            float x  = xlab;
            float l1 = log1pf(__expf(-fabsf(x)));
            pos = -(fmaxf(-x, 0.0f) + l1);                    // log_sigmoid(x)
            bool uniq = true;
            #pragma unroll
            for (int j = 0; j < KLBL; j++)
                if (j < tid && slab[j] == mylab) uniq = false;
            if (uniq) { corr = fmaxf(x, 0.0f) + l1; U = 1; }  // softplus(x)
        }
        #pragma unroll
        for (int o = 16; o > 0; o >>= 1) {
            pos  += __shfl_down_sync(0xFFFFFFFF, pos,  o);
            corr += __shfl_down_sync(0xFFFFFFFF, corr, o);
            U    += __shfl_down_sync(0xFFFFFFFF, U,    o);
        }
        if (tid == 0) {
            g_part[row] = sbuf[0] - corr;
            g_aux[row]  = pos * (1.0f / (float)KLBL);
            g_cnt[row]  = (float)(NCLS - U);
        }
    }

    // last-block election + deterministic final combine
    if (tid == 0) {
        __threadfence();
        int t = atomicAdd(&g_counter, 1);
        isLast = (t == NBLK - 1);
    }
    __syncthreads();
    if (isLast) {
        float acc = 0.0f;
        for (int r = tid; r < BATCH; r += TPB)
            acc += g_aux[r] - g_part[r] / g_cnt[r];
        __syncthreads();
        sbuf[tid] = acc;
        __syncthreads();
        #pragma unroll
        for (int r = TPB / 2; r > 0; r >>= 1) {
            if (tid < r) sbuf[tid] += sbuf[tid + r];
            __syncthreads();
        }
        if (tid == 0) {
            out[0] = -sbuf[0] / (float)BATCH;
            g_counter = 0;          // reset for next graph replay
        }
    }
}

extern "C" void kernel_launch(void* const* d_in, const int* in_sizes, int n_in,
                              void* d_out, int out_size)
{
    const float* inputs  = (const float*)d_in[0];
    const int*   targets = (const int*)d_in[1];
    float*       out     = (float*)d_out;

    fused_row<<<NBLK, TPB>>>(inputs, targets, out);
}

// round 15
// speedup vs baseline: 1.0534x; 1.0521x over previous
#include <cuda_runtime.h>
#include <cuda_bf16.h>

#define BATCH   2048
#define KLBL    20
#define NCLS    50257
#define TPB     512
#define NBLOCKS 592                    // 4 blocks/SM * 148 SMs = ONE wave
#define N4TOT   25731584               // (2048*50257)/4  (exact)
#define SPAN4   43466                  // ceil(N4TOT / NBLOCKS)
#define MAXR    5                      // rows touched per slice <= 5

// Scratch (no cudaMalloc allowed)
__device__ float g_s0  [BATCH];        // row softplus partial, start-owner
__device__ float g_s1  [BATCH];        // row softplus partial, continuation (or 0)
__device__ float g_corr[BATCH];        // dedup'd label softplus correction
__device__ float g_aux [BATCH];        // pos_mean per row
__device__ float g_cnt [BATCH];        // NCLS - U per row
__device__ int   g_counter = 0;        // last-block election; reset each replay

// ---------------------------------------------------------------------------
// exp(x), MUFU-free: magic-round + deg-2 Taylor + FMUL exponent scale.
// Measured loss rel_err 1.1e-4 (R6/R10/R11/R12), 9x inside the 1e-3 gate.
// ---------------------------------------------------------------------------
__device__ __forceinline__ float exp_fast(float x)
{
    float z  = fmaf(x, 1.4426950408889634f, 12582912.0f);   // magic 1.5*2^23
    float nf = z - 12582912.0f;                             // rint(x*log2e)
    float t  = fmaf(nf, -0.6931471805599453f, x);           // |t| <= 0.347
    float q  = fmaf(t, 0.5f, 1.0f);
    q = fmaf(q, t, 1.0f);                                   // 1 + t + t^2/2
    int sbits = (__float_as_int(z) << 23) + 0x3F800000;     // 2^n (wraps exact)
    return q * __int_as_float(sbits);
}

__device__ __forceinline__ void renorm(float& P, int& E)
{
    int b = __float_as_int(P);
    E += (b >> 23) - 127;
    P  = __int_as_float((b & 0x007FFFFF) | 0x3F800000);     // mantissa [1,2)
}

// per-thread partial of sum_{j in [lo,hi)} softplus(in[j])  (R2 loop shape)
__device__ __forceinline__ float frag_val(const float* __restrict__ in,
                                          int lo, int hi, int tid)
{
    float Pa = 1.0f, Pb = 1.0f;
    int   Ea = 0,   Eb = 0;

    int a = (lo + 3) & ~3;                         // align to float4
    if (a > hi) a = hi;
    for (int j = lo + tid; j < a; j += TPB) {      // head (<=3)
        Pa = fmaf(exp_fast(in[j]), Pa, Pa); renorm(Pa, Ea);
    }
    const int n4 = (hi - a) >> 2;
    const float4* v = (const float4*)(in + a);
    int i = tid;
    for (; i + TPB < n4; i += 2 * TPB) {
        float4 xa = v[i];
        float4 xb = v[i + TPB];
        Pa = fmaf(exp_fast(xa.x), Pa, Pa);
        Pa = fmaf(exp_fast(xa.y), Pa, Pa);
        Pb = fmaf(exp_fast(xa.z), Pb, Pb);
        Pb = fmaf(exp_fast(xa.w), Pb, Pb);
        Pa = fmaf(exp_fast(xb.x), Pa, Pa);
        Pa = fmaf(exp_fast(xb.y), Pa, Pa);
        Pb = fmaf(exp_fast(xb.z), Pb, Pb);
        Pb = fmaf(exp_fast(xb.w), Pb, Pb);
        renorm(Pa, Ea);
        renorm(Pb, Eb);
    }
    if (i < n4) {
        float4 xa = v[i];
        Pa = fmaf(exp_fast(xa.x), Pa, Pa);
        Pa = fmaf(exp_fast(xa.y), Pa, Pa);
        Pb = fmaf(exp_fast(xa.z), Pb, Pb);
        Pb = fmaf(exp_fast(xa.w), Pb, Pb);
        renorm(Pa, Ea);
        renorm(Pb, Eb);
    }
    const int t0 = a + (n4 << 2);
    for (int j = t0 + tid; j < hi; j += TPB) {     // tail (<=3)
        Pa = fmaf(exp_fast(in[j]), Pa, Pa); renorm(Pa, Ea);
    }
    return fmaf((float)(Ea + Eb), 0.69314718055994531f, __logf(Pa * Pb));
}

// ---------------------------------------------------------------------------
// Persistent single-wave stream: block b owns float4s [b*SPAN4, (b+1)*SPAN4).
// ---------------------------------------------------------------------------
__global__ __launch_bounds__(TPB, 4)
void fused_stream(const float* __restrict__ in, const int* __restrict__ tgt,
                  float* __restrict__ out)
{
    const int b   = blockIdx.x;
    const int tid = threadIdx.x;

    const int f4lo = b * SPAN4;
    const int f4hi = (f4lo + SPAN4 < N4TOT) ? f4lo + SPAN4 : N4TOT;
    const int flo  = f4lo << 2;
    const int fhi  = f4hi << 2;
    const int rlo  = flo / NCLS;
    const int rhi  = (fhi - 1) / NCLS;
    const int r0   = (flo + NCLS - 1) / NCLS;      // first row STARTING in span
    const int cnt0 = rhi - r0 + 1;                 // slot-0 rows (1..4)
    const int nr   = rhi - rlo + 1;                // fragments (1..5)

    __shared__ float sbuf[MAXR][TPB];              // 10 KB
    __shared__ int   slabv[4 * KLBL];
    __shared__ float sxv  [4 * KLBL];
    __shared__ int   isLast;

    // early label prefetch for slot-0 rows (hidden under the stream)
    if (tid < cnt0 * KLBL) {
        int rr  = r0 + tid / KLBL;
        int k   = tid % KLBL;
        int lab = tgt[rr * KLBL + k];
        slabv[tid] = lab;
        sxv[tid]   = in[(size_t)rr * NCLS + lab];
    }

    // fragments: intersection of span with each touched row
    for (int r = rlo; r <= rhi; r++) {
        int lo = r * NCLS;      if (lo < flo) lo = flo;
        int hi = (r + 1) * NCLS; if (hi > fhi) hi = fhi;
        sbuf[r - rlo][tid] = frag_val(in, lo, hi, tid);
    }
    __syncthreads();

    // one tree reduce over all fragments simultaneously
    for (int s = TPB / 2; s > 0; s >>= 1) {
        if (tid < s)
            for (int k = 0; k < nr; k++)
                sbuf[k][tid] += sbuf[k][tid + s];
        __syncthreads();
    }

    // write per-row partial slots (deterministic fixed slots)
    if (tid < nr) {
        int   r  = rlo + tid;
        float fv = sbuf[tid][0];
        long  rs = (long)r * NCLS;
        long  re = rs + NCLS;
        if (rs >= flo) {                 // this block owns the row start
            g_s0[r] = fv;
            if (re <= fhi) g_s1[r] = 0.0f;   // fully contained: no continuation
        } else {
            g_s1[r] = fv;                // continuation from previous block
        }
    }

    // label pass on warp 0 for each slot-0 row (accurate math, 20 elems)
    if (tid < 32) {
        for (int j = 0; j < cnt0; j++) {
            int   r   = r0 + j;
            float pos = 0.0f, corr = 0.0f;
            int   U   = 0;
            if (tid < KLBL) {
                float x   = sxv[j * KLBL + tid];
                int   lab = slabv[j * KLBL + tid];
                float l1  = log1pf(__expf(-fabsf(x)));
                pos = -(fmaxf(-x, 0.0f) + l1);               // log_sigmoid(x)
                bool uniq = true;
                #pragma unroll
                for (int k2 = 0; k2 < KLBL; k2++)
                    if (k2 < tid && slabv[j * KLBL + k2] == lab) uniq = false;
                if (uniq) { corr = fmaxf(x, 0.0f) + l1; U = 1; }
            }
            #pragma unroll
            for (int o = 16; o > 0; o >>= 1) {
                pos  += __shfl_down_sync(0xFFFFFFFF, pos,  o);
                corr += __shfl_down_sync(0xFFFFFFFF, corr, o);
                U    += __shfl_down_sync(0xFFFFFFFF, U,    o);
            }
            if (tid == 0) {
                g_aux [r] = pos * (1.0f / (float)KLBL);
                g_corr[r] = corr;
                g_cnt [r] = (float)(NCLS - U);
            }
        }
    }

    // last-block election + deterministic final combine
    if (tid == 0) {
        __threadfence();
        int t = atomicAdd(&g_counter, 1);
        isLast = (t == NBLOCKS - 1);
    }
    __syncthreads();
    if (isLast) {
        float acc = 0.0f;
        for (int r = tid; r < BATCH; r += TPB) {
            float S = g_s0[r] + g_s1[r] - g_corr[r];
            acc += g_aux[r] - S / g_cnt[r];
        }
        __syncthreads();
        sbuf[0][tid] = acc;
        __syncthreads();
        #pragma unroll
        for (int s = TPB / 2; s > 0; s >>= 1) {
            if (tid < s) sbuf[0][tid] += sbuf[0][tid + s];
            __syncthreads();
        }
        if (tid == 0) {
            out[0] = -sbuf[0][0] / (float)BATCH;
            g_counter = 0;                 // reset for next graph replay
        }
    }
}

extern "C" void kernel_launch(void* const* d_in, const int* in_sizes, int n_in,
                              void* d_out, int out_size)
{
    const float* inputs  = (const float*)d_in[0];
    const int*   targets = (const int*)d_in[1];
    float*       out     = (float*)d_out;

    fused_stream<<<NBLOCKS, TPB>>>(inputs, targets, out);
}